// round 15
// baseline (speedup 1.0000x reference)
#include <cuda_runtime.h>
#include <cuda_bf16.h>
#include <math.h>
#include <stdint.h>
#include <cstdint>

// ---------------------------------------------------------------------------
// Problem constants
// ---------------------------------------------------------------------------
#define BB   2
#define LL   2048
#define DM   1024
#define DI   2048
#define DS   16
#define DR   64
#define DCONV 4
#define NXP  96
#define NXPP 128
#define MROWS (BB*LL)
#define SEG  8
#define SLEN (LL/SEG)               // 256
#define NCHG (DI/32)                // 64 channel groups
#define CTL  8                      // conv timesteps per thread
#define LOG2E 1.44269504088896f

// ---------------------------------------------------------------------------
// Scratch (device globals — no allocation allowed)
// ---------------------------------------------------------------------------
__device__ float g_xdbl [(size_t)BB*LL*NXPP];        // fp32 x_dbl (B,C for scan)
__device__ float g_P    [(size_t)2*MROWS*NXPP];      // GEMM2 split-K partials
__device__ float g_hseg [(size_t)BB*SEG*DI*DS];      // inclusive seg-end states
__device__ int   g_sflag[BB*SEG*NCHG];               // publication flags

__device__ __nv_bfloat16 g_xh  [(size_t)MROWS*DM];   // x bf16 (GEMM1 A)
__device__ __nv_bfloat16 g_w1h [(size_t)DM*2*DI];    // W_in bf16
__device__ __nv_bfloat16 g_xzh [(size_t)MROWS*2*DI]; // xz bf16: [0:DI]=xin, [DI:2DI]=z
__device__ __nv_bfloat16 g_uh  [(size_t)MROWS*DI];   // u bf16
__device__ __nv_bfloat16 g_wxh [(size_t)DI*NXPP];    // W_xproj padded bf16
__device__ __nv_bfloat16 g_xdh [(size_t)MROWS*NXPP]; // x_dbl bf16 (GEMM4 A)
__device__ __nv_bfloat16 g_wdh [(size_t)DR*DI];      // W_dt bf16
__device__ __nv_bfloat16 g_dth [(size_t)MROWS*DI];   // dt bf16
__device__ __nv_bfloat16 g_yh  [(size_t)MROWS*DI];   // y bf16
__device__ __nv_bfloat16 g_woh [(size_t)DI*DM];      // W_out bf16

// ---------------------------------------------------------------------------
// PTX helpers
// ---------------------------------------------------------------------------
__device__ __forceinline__ unsigned cvta_s(const void* p) {
    return (unsigned)__cvta_generic_to_shared(p);
}
__device__ __forceinline__ void ldsm4(unsigned* r, unsigned a) {
    asm volatile("ldmatrix.sync.aligned.m8n8.x4.shared.b16 {%0,%1,%2,%3}, [%4];"
        : "=r"(r[0]), "=r"(r[1]), "=r"(r[2]), "=r"(r[3]) : "r"(a));
}
__device__ __forceinline__ void ldsm4t(unsigned* r, unsigned a) {
    asm volatile("ldmatrix.sync.aligned.m8n8.x4.trans.shared.b16 {%0,%1,%2,%3}, [%4];"
        : "=r"(r[0]), "=r"(r[1]), "=r"(r[2]), "=r"(r[3]) : "r"(a));
}
__device__ __forceinline__ void mma16816(float* d, const unsigned* a, const unsigned* b) {
    asm volatile("mma.sync.aligned.m16n8k16.row.col.f32.bf16.bf16.f32 "
        "{%0,%1,%2,%3}, {%4,%5,%6,%7}, {%8,%9}, {%0,%1,%2,%3};"
        : "+f"(d[0]), "+f"(d[1]), "+f"(d[2]), "+f"(d[3])
        : "r"(a[0]), "r"(a[1]), "r"(a[2]), "r"(a[3]), "r"(b[0]), "r"(b[1]));
}
__device__ __forceinline__ void cpa16(void* s, const void* g) {
    unsigned sa = cvta_s(s);
    asm volatile("cp.async.cg.shared.global [%0], [%1], 16;" :: "r"(sa), "l"(g));
}
__device__ __forceinline__ void cpcommit() {
    asm volatile("cp.async.commit_group;");
}
template<int N>
__device__ __forceinline__ void cpwait() {
    asm volatile("cp.async.wait_group %0;" :: "n"(N));
}

// ---------------------------------------------------------------------------
// bf16 tensor-core GEMM, cp.async 3-stage pipeline, ONE sync per K-tile.
// CTA tile (64*MF) x 128 x 32; 8 warps (4x2), warp tile (16*MF) x 64.
// EPI: 0 plain fp32 C; 2 +bias[col] softplus -> bf16 Chi;
//      3 +E0 residual -> fp32 C; 4 bf16 Chi only.
// ---------------------------------------------------------------------------
template<int MF, int EPI>
__global__ __launch_bounds__(256) void gemm_bf16(
    const __nv_bfloat16* __restrict__ A, int lda,
    const __nv_bfloat16* __restrict__ B, int ldb,
    float* __restrict__ C, int ldc, int K,
    const float* __restrict__ E0,
    __nv_bfloat16* __restrict__ Chi,
    size_t partStride)
{
    const int BM = 64 * MF;
    const int LDA = 40;
    const int LDB = 136;
    const int A_SZ = BM * LDA;
    const int B_SZ = 32 * LDB;
    const int STAGE = A_SZ + B_SZ;

    extern __shared__ __nv_bfloat16 smem[];

    const int tid  = threadIdx.x;
    const int lane = tid & 31;
    const int wid  = tid >> 5;
    const int wm   = (wid >> 1) * (16 * MF);
    const int wn   = (wid & 1) * 64;
    const int bm   = blockIdx.y * BM;
    const int bn   = blockIdx.x * 128;
    const int kbase = blockIdx.z * K;
    C += (size_t)blockIdx.z * partStride;

    __nv_bfloat16* sA[3];
    __nv_bfloat16* sB[3];
    #pragma unroll
    for (int s = 0; s < 3; s++) {
        sA[s] = smem + s * STAGE;
        sB[s] = sA[s] + A_SZ;
    }

    float acc[MF][8][4];
    #pragma unroll
    for (int i = 0; i < MF; i++) {
        #pragma unroll
        for (int j = 0; j < 8; j++) {
            #pragma unroll
            for (int q = 0; q < 4; q++) acc[i][j][q] = 0.f;
        }
    }

    unsigned aB[3], bB[3];
    #pragma unroll
    for (int s = 0; s < 3; s++) {
        aB[s] = cvta_s(sA[s] + (wm + (lane & 15)) * LDA + ((lane >> 4) << 3));
        bB[s] = cvta_s(sB[s] + (lane & 15) * LDB + wn + ((lane >> 4) << 3));
    }

    const int ar = tid >> 2;
    const int ac = (tid & 3) * 8;
    const int br = tid >> 4;
    const int bc = (tid & 15) * 8;

    const int T = K / 32;

    #define ISSUE_TILE(t_)                                                          \
    {                                                                               \
        const int st_ = (t_) % 3;                                                   \
        const int k0_ = kbase + (t_) * 32;                                          \
        _Pragma("unroll")                                                           \
        for (int p = 0; p < MF; p++) {                                              \
            const int row = p * 64 + ar;                                            \
            cpa16(sA[st_] + row * LDA + ac, A + (size_t)(bm + row) * lda + k0_ + ac); \
        }                                                                           \
        _Pragma("unroll")                                                           \
        for (int p = 0; p < 2; p++) {                                               \
            const int row = p * 16 + br;                                            \
            cpa16(sB[st_] + row * LDB + bc, B + (size_t)(k0_ + row) * ldb + bn + bc); \
        }                                                                           \
        cpcommit();                                                                 \
    }

    ISSUE_TILE(0);
    if (T > 1) ISSUE_TILE(1);

    for (int t = 0; t < T; t++) {
        if (t + 2 < T) {
            cpwait<1>();
        } else {
            cpwait<0>();
        }
        __syncthreads();
        if (t + 2 < T) ISSUE_TILE(t + 2);

        const int st = t % 3;
        #pragma unroll
        for (int s = 0; s < 2; s++) {
            unsigned af[MF][4];
            #pragma unroll
            for (int mi = 0; mi < MF; mi++)
                ldsm4(af[mi], aB[st] + (unsigned)((mi * 16 * LDA + s * 16) * 2));
            unsigned bf[8][2];
            #pragma unroll
            for (int pr = 0; pr < 4; pr++) {
                unsigned t4[4];
                ldsm4t(t4, bB[st] + (unsigned)((s * 16 * LDB + pr * 16) * 2));
                bf[2 * pr][0] = t4[0]; bf[2 * pr][1] = t4[1];
                bf[2 * pr + 1][0] = t4[2]; bf[2 * pr + 1][1] = t4[3];
            }
            #pragma unroll
            for (int mi = 0; mi < MF; mi++) {
                #pragma unroll
                for (int nj = 0; nj < 8; nj++)
                    mma16816(acc[mi][nj], af[mi], bf[nj]);
            }
        }
    }
    #undef ISSUE_TILE

    // ---- epilogue ----
    #pragma unroll
    for (int mi = 0; mi < MF; mi++) {
        #pragma unroll
        for (int nj = 0; nj < 8; nj++) {
            const int r0 = bm + wm + mi * 16 + (lane >> 2);
            const int c  = bn + wn + nj * 8 + (lane & 3) * 2;
            #pragma unroll
            for (int hh = 0; hh < 2; hh++) {
                const int r = r0 + hh * 8;
                float vx = acc[mi][nj][2 * hh];
                float vy = acc[mi][nj][2 * hh + 1];
                if (EPI == 2) {
                    vx += E0[c];
                    vy += E0[c + 1];
                    vx = (vx > 20.f) ? vx : log1pf(expf(vx));
                    vy = (vy > 20.f) ? vy : log1pf(expf(vy));
                }
                if (EPI == 3) {
                    const float2 rr = *(const float2*)&E0[(size_t)r * ldc + c];
                    vx += rr.x;
                    vy += rr.y;
                }
                if (EPI == 0 || EPI == 3) {
                    float2 v2; v2.x = vx; v2.y = vy;
                    *(float2*)&C[(size_t)r * ldc + c] = v2;
                }
                if (EPI == 2 || EPI == 4) {
                    __nv_bfloat162 hv;
                    hv.x = __float2bfloat16(vx);
                    hv.y = __float2bfloat16(vy);
                    *(__nv_bfloat162*)&Chi[(size_t)r * ldc + c] = hv;
                }
            }
        }
    }
}

// ---------------------------------------------------------------------------
// GEMM2 split-K reduce: xdbl = p0 + p1 (fp32), xdh = bf16. Also clears
// the scan chain flags (runs before scan_fused each replay).
// ---------------------------------------------------------------------------
__global__ void reduce_xdbl()
{
    const int gi = blockIdx.x * blockDim.x + threadIdx.x;
    if (gi < BB * SEG * NCHG) g_sflag[gi] = 0;
    const int i = gi * 4;
    if (i >= MROWS * NXPP) return;
    float4 a = *(const float4*)&g_P[i];
    float4 b = *(const float4*)&g_P[(size_t)MROWS * NXPP + i];
    float4 v;
    v.x = a.x + b.x; v.y = a.y + b.y; v.z = a.z + b.z; v.w = a.w + b.w;
    *(float4*)&g_xdbl[i] = v;
    __nv_bfloat162 h0; h0.x = __float2bfloat16(v.x); h0.y = __float2bfloat16(v.y);
    __nv_bfloat162 h1; h1.x = __float2bfloat16(v.z); h1.y = __float2bfloat16(v.w);
    *(__nv_bfloat162*)&g_xdh[i]     = h0;
    *(__nv_bfloat162*)&g_xdh[i + 2] = h1;
}

// ---------------------------------------------------------------------------
// Fused conversions: x, W_in, W_out, W_dt in one launch (each n % 4 == 0)
// ---------------------------------------------------------------------------
__global__ void cvt_all(
    const float* __restrict__ s0, __nv_bfloat16* __restrict__ d0, int n0,
    const float* __restrict__ s1, __nv_bfloat16* __restrict__ d1, int n1,
    const float* __restrict__ s2, __nv_bfloat16* __restrict__ d2, int n2,
    const float* __restrict__ s3, __nv_bfloat16* __restrict__ d3, int n3)
{
    int i = (blockIdx.x * blockDim.x + threadIdx.x) * 4;
    const float* s; __nv_bfloat16* d;
    if (i < n0)                { s = s0 + i;               d = d0 + i; }
    else if (i < n0 + n1)      { s = s1 + (i - n0);        d = d1 + (i - n0); }
    else if (i < n0 + n1 + n2) { s = s2 + (i - n0 - n1);   d = d2 + (i - n0 - n1); }
    else if (i < n0 + n1 + n2 + n3) { s = s3 + (i - n0 - n1 - n2); d = d3 + (i - n0 - n1 - n2); }
    else return;
    float4 v = *(const float4*)s;
    __nv_bfloat162 hA; hA.x = __float2bfloat16(v.x); hA.y = __float2bfloat16(v.y);
    __nv_bfloat162 hB; hB.x = __float2bfloat16(v.z); hB.y = __float2bfloat16(v.w);
    *(__nv_bfloat162*)(d)     = hA;
    *(__nv_bfloat162*)(d + 2) = hB;
}

__global__ void pad_cvt_wxproj(const float* __restrict__ W)
{
    int idx = blockIdx.x * blockDim.x + threadIdx.x;
    if (idx >= DI * NXPP) return;
    int row = idx / NXPP;
    int col = idx % NXPP;
    float v = (col < NXP) ? W[row * NXP + col] : 0.f;
    g_wxh[idx] = __float2bfloat16(v);
}

// ---------------------------------------------------------------------------
// Causal depthwise conv (k=4) + bias + silu, register-tiled (CTL=8 steps/thr)
// ---------------------------------------------------------------------------
__global__ __launch_bounds__(256) void conv_silu(
    const float* __restrict__ cw, const float* __restrict__ cb)
{
    const size_t total = (size_t)BB * (LL / CTL) * (DI / 2);
    size_t idx = (size_t)blockIdx.x * blockDim.x + threadIdx.x;
    if (idx >= total) return;
    const int d2 = (int)(idx % (DI / 2)) * 2;
    const int lt = (int)((idx / (DI / 2)) % (LL / CTL));
    const int b  = (int)(idx / ((size_t)(LL / CTL) * (DI / 2)));
    const int l0 = lt * CTL;

    float w0[DCONV], w1[DCONV];
    #pragma unroll
    for (int j = 0; j < DCONV; j++) {
        w0[j] = cw[d2 * DCONV + j];
        w1[j] = cw[(d2 + 1) * DCONV + j];
    }
    const float b0 = cb[d2];
    const float b1 = cb[d2 + 1];

    const __nv_bfloat162* base = (const __nv_bfloat162*)
        (g_xzh + ((size_t)b * LL) * (2 * DI) + d2);
    float x0[CTL + 3], x1[CTL + 3];
    #pragma unroll
    for (int j = 0; j < CTL + 3; j++) {
        const int ls = l0 - 3 + j;
        if (ls >= 0) {
            __nv_bfloat162 xv = base[(size_t)ls * DI];
            x0[j] = __bfloat162float(xv.x);
            x1[j] = __bfloat162float(xv.y);
        } else {
            x0[j] = 0.f;
            x1[j] = 0.f;
        }
    }

    __nv_bfloat162* up = (__nv_bfloat162*)(g_uh + ((size_t)b * LL + l0) * DI + d2);
    #pragma unroll
    for (int t = 0; t < CTL; t++) {
        float a0 = b0, a1 = b1;
        #pragma unroll
        for (int j = 0; j < DCONV; j++) {
            a0 = fmaf(w0[j], x0[t + j], a0);
            a1 = fmaf(w1[j], x1[t + j], a1);
        }
        const float s0 = 1.f / (1.f + __expf(-a0));
        const float s1 = 1.f / (1.f + __expf(-a1));
        __nv_bfloat162 o;
        o.x = __float2bfloat16(a0 * s0);
        o.y = __float2bfloat16(a1 * s1);
        up[(size_t)t * (DI / 2)] = o;
    }
}

// ---------------------------------------------------------------------------
// Fused single-pass chained selective scan. SEG=8 (256-step segments).
// grid(NCHG, BB, SEG) — z (seg) varies slowest so predecessors dispatch first.
// ---------------------------------------------------------------------------
__global__ __launch_bounds__(128) void scan_fused(
    const float* __restrict__ A_log, const float* __restrict__ Dvec)
{
    extern __shared__ char smraw[];
    __nv_bfloat16 (*sdt)[32] = (__nv_bfloat16(*)[32])(smraw);
    __nv_bfloat16 (*su )[32] = (__nv_bfloat16(*)[32])(smraw + 16384);
    __nv_bfloat16 (*sz )[32] = (__nv_bfloat16(*)[32])(smraw + 32768);
    float         (*sB )[16] = (float(*)[16])        (smraw + 49152);
    float         (*sC )[16] = (float(*)[16])        (smraw + 65536);

    const int chg = blockIdx.x;
    const int b   = blockIdx.y;
    const int seg = blockIdx.z;
    const int chB = chg * 32;
    const int tid = threadIdx.x;
    const size_t rowBase = (size_t)b * LL + (size_t)seg * SLEN;

    for (int i = tid; i < SLEN * 32; i += 128) {
        int t = i >> 5, c = i & 31;
        sdt[t][c] = g_dth[(rowBase + t) * DI + chB + c];
        su [t][c] = g_uh [(rowBase + t) * DI + chB + c];
        sz [t][c] = g_xzh[(rowBase + t) * (2 * DI) + DI + chB + c];
    }
    for (int i = tid; i < SLEN * 16; i += 128) {
        int t = i >> 4, c = i & 15;
        sB[t][c] = g_xdbl[(rowBase + t) * NXPP + DR + c];
        sC[t][c] = g_xdbl[(rowBase + t) * NXPP + DR + DS + c];
    }
    __syncthreads();

    const int chl = tid >> 2;
    const int ch  = chB + chl;
    const int sg  = tid & 3;
    const int n0  = sg * 4;

    float Ae[4], h[4];
    #pragma unroll
    for (int j = 0; j < 4; j++) {
        Ae[j] = -expf(A_log[ch * DS + n0 + j]) * LOG2E;
        h[j] = 0.f;
    }
    float sumdt = 0.f;

    // ---- local scan (h from 0) ----
    for (int t = 0; t < SLEN; t++) {
        const float dtv = __bfloat162float(sdt[t][chl]);
        const float uv  = __bfloat162float(su[t][chl]);
        const float du  = dtv * uv;
        sumdt += dtv;
        float4 B4 = *(const float4*)&sB[t][n0];
        h[0] = fmaf(exp2f(dtv * Ae[0]), h[0], du * B4.x);
        h[1] = fmaf(exp2f(dtv * Ae[1]), h[1], du * B4.y);
        h[2] = fmaf(exp2f(dtv * Ae[2]), h[2], du * B4.z);
        h[3] = fmaf(exp2f(dtv * Ae[3]), h[3], du * B4.w);
    }

    float P4[4];
    #pragma unroll
    for (int j = 0; j < 4; j++) P4[j] = exp2f(sumdt * Ae[j]);

    // ---- chain: acquire h_in from predecessor, publish inclusive h_out ----
    const size_t hcur = (((size_t)b * SEG + seg) * DI + ch) * DS + n0;
    const int fcur = (b * SEG + seg) * NCHG + chg;
    float hin[4] = {0.f, 0.f, 0.f, 0.f};

    if (seg > 0) {
        const int fprev = fcur - NCHG;
        if (tid == 0) {
            volatile int* fp = &g_sflag[fprev];
            while (*fp == 0) { __nanosleep(64); }
        }
        __syncthreads();
        __threadfence();
        const size_t hprev = hcur - (size_t)DI * DS;
        float4 h4 = *(const float4*)&g_hseg[hprev];
        hin[0] = h4.x; hin[1] = h4.y; hin[2] = h4.z; hin[3] = h4.w;
    }

    {
        float4 ho;
        ho.x = fmaf(P4[0], hin[0], h[0]);
        ho.y = fmaf(P4[1], hin[1], h[1]);
        ho.z = fmaf(P4[2], hin[2], h[2]);
        ho.w = fmaf(P4[3], hin[3], h[3]);
        *(float4*)&g_hseg[hcur] = ho;
    }
    __threadfence();
    __syncthreads();
    if (tid == 0) g_sflag[fcur] = 1;

    // ---- rescan from hin, emit y ----
    const float Dv = Dvec[ch];
    h[0] = hin[0]; h[1] = hin[1]; h[2] = hin[2]; h[3] = hin[3];
    __nv_bfloat16* yph = g_yh + rowBase * DI + ch;

    for (int t = 0; t < SLEN; t++) {
        const float dtv = __bfloat162float(sdt[t][chl]);
        const float uv  = __bfloat162float(su[t][chl]);
        const float du  = dtv * uv;
        float4 B4 = *(const float4*)&sB[t][n0];
        float4 C4 = *(const float4*)&sC[t][n0];
        h[0] = fmaf(exp2f(dtv * Ae[0]), h[0], du * B4.x);
        h[1] = fmaf(exp2f(dtv * Ae[1]), h[1], du * B4.y);
        h[2] = fmaf(exp2f(dtv * Ae[2]), h[2], du * B4.z);
        h[3] = fmaf(exp2f(dtv * Ae[3]), h[3], du * B4.w);

        float yv = h[0] * C4.x;
        yv = fmaf(h[1], C4.y, yv);
        yv = fmaf(h[2], C4.z, yv);
        yv = fmaf(h[3], C4.w, yv);
        yv += __shfl_xor_sync(0xffffffffu, yv, 1);
        yv += __shfl_xor_sync(0xffffffffu, yv, 2);

        if (sg == 0) {
            const float zv  = __bfloat162float(sz[t][chl]);
            const float ys  = fmaf(uv, Dv, yv);
            const float sig = 1.f / (1.f + __expf(-zv));
            const float yo  = ys * (zv * sig);
            yph[(size_t)t * DI] = __float2bfloat16(yo);
        }
    }
}

// ---------------------------------------------------------------------------
// In-place row LayerNorm on d_out (4096 rows x 1024)
// ---------------------------------------------------------------------------
__global__ __launch_bounds__(256) void ln_kernel(
    float* __restrict__ out, const float* __restrict__ gamma,
    const float* __restrict__ beta)
{
    __shared__ float red[8];
    const int row = blockIdx.x;
    float* p = out + (size_t)row * DM;
    const int tid  = threadIdx.x;
    const int lane = tid & 31;
    const int warp = tid >> 5;

    float v[4];
    float s = 0.f;
    #pragma unroll
    for (int i = 0; i < 4; i++) { v[i] = p[tid + 256 * i]; s += v[i]; }
    #pragma unroll
    for (int o = 16; o > 0; o >>= 1) s += __shfl_xor_sync(0xffffffffu, s, o);
    if (lane == 0) red[warp] = s;
    __syncthreads();
    s = 0.f;
    #pragma unroll
    for (int w = 0; w < 8; w++) s += red[w];
    const float mu = s * (1.f / DM);
    __syncthreads();

    float s2 = 0.f;
    #pragma unroll
    for (int i = 0; i < 4; i++) { float d = v[i] - mu; s2 += d * d; }
    #pragma unroll
    for (int o = 16; o > 0; o >>= 1) s2 += __shfl_xor_sync(0xffffffffu, s2, o);
    if (lane == 0) red[warp] = s2;
    __syncthreads();
    s2 = 0.f;
    #pragma unroll
    for (int w = 0; w < 8; w++) s2 += red[w];
    const float rstd = rsqrtf(s2 * (1.f / DM) + 1e-5f);

    #pragma unroll
    for (int i = 0; i < 4; i++) {
        const int col = tid + 256 * i;
        p[col] = (v[i] - mu) * rstd * gamma[col] + beta[col];
    }
}

// ---------------------------------------------------------------------------
// Launcher
// ---------------------------------------------------------------------------
extern "C" void kernel_launch(void* const* d_in, const int* in_sizes, int n_in,
                              void* d_out, int out_size)
{
    const float* x      = (const float*)d_in[0];
    const float* W_in   = (const float*)d_in[1];
    const float* conv_w = (const float*)d_in[2];
    const float* conv_b = (const float*)d_in[3];
    const float* W_xprj = (const float*)d_in[4];
    const float* W_dt   = (const float*)d_in[5];
    const float* b_dt   = (const float*)d_in[6];
    const float* A_log  = (const float*)d_in[7];
    const float* Dvec   = (const float*)d_in[8];
    const float* W_out  = (const float*)d_in[9];
    const float* gamma  = (const float*)d_in[10];
    const float* beta   = (const float*)d_in[11];
    float* out = (float*)d_out;

    float *P;
    cudaGetSymbolAddress((void**)&P, g_P);
    __nv_bfloat16 *xh, *w1h, *xzh, *uh, *wxh, *xdh, *wdh, *dth, *yh, *woh;
    cudaGetSymbolAddress((void**)&xh,  g_xh);
    cudaGetSymbolAddress((void**)&w1h, g_w1h);
    cudaGetSymbolAddress((void**)&xzh, g_xzh);
    cudaGetSymbolAddress((void**)&uh,  g_uh);
    cudaGetSymbolAddress((void**)&wxh, g_wxh);
    cudaGetSymbolAddress((void**)&xdh, g_xdh);
    cudaGetSymbolAddress((void**)&wdh, g_wdh);
    cudaGetSymbolAddress((void**)&dth, g_dth);
    cudaGetSymbolAddress((void**)&yh,  g_yh);
    cudaGetSymbolAddress((void**)&woh, g_woh);

    // dynamic smem sizes (bytes)
    const int SM_MF2 = 3 * (128 * 40 + 32 * 136) * 2;            // 56832
    const int SM_MF1 = 3 * (64 * 40 + 32 * 136) * 2;             // 41472
    const int SM_SC  = 81920;                                    // SEG=8 staging
    cudaFuncSetAttribute(gemm_bf16<2,4>, cudaFuncAttributeMaxDynamicSharedMemorySize, SM_MF2);
    cudaFuncSetAttribute(gemm_bf16<1,0>, cudaFuncAttributeMaxDynamicSharedMemorySize, SM_MF1);
    cudaFuncSetAttribute(gemm_bf16<2,2>, cudaFuncAttributeMaxDynamicSharedMemorySize, SM_MF2);
    cudaFuncSetAttribute(gemm_bf16<2,3>, cudaFuncAttributeMaxDynamicSharedMemorySize, SM_MF2);
    cudaFuncSetAttribute(scan_fused,     cudaFuncAttributeMaxDynamicSharedMemorySize, SM_SC);

    // 0) conversions (one fused launch + pad)
    {
        const int n0 = MROWS * DM;         // x
        const int n1 = DM * 2 * DI;        // W_in
        const int n2 = DI * DM;            // W_out
        const int n3 = DR * DI;            // W_dt
        const int total4 = (n0 + n1 + n2 + n3) / 4;
        cvt_all<<<(total4 + 255) / 256, 256>>>(x, xh, n0, W_in, w1h, n1,
                                               W_out, woh, n2, W_dt, wdh, n3);
        pad_cvt_wxproj<<<(DI * NXPP + 255) / 256, 256>>>(W_xprj);
    }

    // 1) GEMM1: xz = x @ W_in -> bf16  (M=4096, N=4096, K=1024)
    {
        dim3 grid(2 * DI / 128, MROWS / 128);
        gemm_bf16<2, 4><<<grid, 256, SM_MF2>>>(xh, DM, w1h, 2 * DI,
                                               nullptr, 2 * DI, DM, nullptr, xzh, 0);
    }

    // 2) conv + silu -> u (bf16), register-tiled
    {
        size_t n = (size_t)BB * (LL / CTL) * (DI / 2);
        conv_silu<<<(unsigned)((n + 255) / 256), 256>>>(conv_w, conv_b);
    }

    // 3) GEMM2: x_dbl partials, split-K=2 -> g_P; reduce (+flag clear)
    {
        dim3 grid(NXPP / 128, MROWS / 64, 2);
        gemm_bf16<1, 0><<<grid, 256, SM_MF1>>>(uh, DI, wxh, NXPP,
                                               P, NXPP, DI / 2, nullptr, nullptr,
                                               (size_t)MROWS * NXPP);
        reduce_xdbl<<<(MROWS * NXPP / 4 + 255) / 256, 256>>>();
    }

    // 4) GEMM4: dt = softplus(dt_low @ W_dt + b_dt) -> bf16  (M=4096, N=2048, K=64)
    {
        dim3 grid(DI / 128, MROWS / 128);
        gemm_bf16<2, 2><<<grid, 256, SM_MF2>>>(xdh, NXPP, wdh, DI,
                                               nullptr, DI, DR, b_dt, dth, 0);
    }

    // 5) fused single-pass chained scan -> y (bf16), SEG=8
    {
        dim3 grid(NCHG, BB, SEG);
        scan_fused<<<grid, 128, SM_SC>>>(A_log, Dvec);
    }

    // 6) GEMM3: out = y @ W_out + x  (M=4096, N=1024, K=2048; fp32 residual)
    {
        dim3 grid(DM / 128, MROWS / 128);
        gemm_bf16<2, 3><<<grid, 256, SM_MF2>>>(yh, DI, woh, DM,
                                               out, DM, DI, x, nullptr, 0);
    }

    // 7) LayerNorm in-place
    ln_kernel<<<MROWS, 256>>>(out, gamma, beta);
}

// round 17
// speedup vs baseline: 1.4244x; 1.4244x over previous
#include <cuda_runtime.h>
#include <cuda_bf16.h>
#include <math.h>
#include <stdint.h>
#include <cstdint>

// ---------------------------------------------------------------------------
// Problem constants
// ---------------------------------------------------------------------------
#define BB   2
#define LL   2048
#define DM   1024
#define DI   2048
#define DS   16
#define DR   64
#define DCONV 4
#define NXP  96
#define NXPP 128
#define MROWS (BB*LL)
#define SEG  16
#define SLEN (LL/SEG)               // 128
#define NCHG (DI/32)                // 64 channel groups
#define CTL  8                      // conv timesteps per thread
#define LOG2E 1.44269504088896f

// ---------------------------------------------------------------------------
// Scratch (device globals — no allocation allowed)
// ---------------------------------------------------------------------------
__device__ float g_xdbl [(size_t)BB*LL*NXPP];        // fp32 x_dbl (B,C for scan)
__device__ float g_P    [(size_t)2*MROWS*NXPP];      // GEMM2 split-K partials
__device__ float g_hseg [(size_t)BB*SEG*DI*DS];      // inclusive seg-end states
__device__ int   g_sflag[BB*SEG*NCHG];               // publication flags

__device__ __nv_bfloat16 g_xh  [(size_t)MROWS*DM];   // x bf16 (GEMM1 A)
__device__ __nv_bfloat16 g_w1h [(size_t)DM*2*DI];    // W_in bf16
__device__ __nv_bfloat16 g_xzh [(size_t)MROWS*2*DI]; // xz bf16: [0:DI]=xin, [DI:2DI]=z
__device__ __nv_bfloat16 g_uh  [(size_t)MROWS*DI];   // u bf16
__device__ __nv_bfloat16 g_wxh [(size_t)DI*NXPP];    // W_xproj padded bf16
__device__ __nv_bfloat16 g_xdh [(size_t)MROWS*NXPP]; // x_dbl bf16 (GEMM4 A)
__device__ __nv_bfloat16 g_wdh [(size_t)DR*DI];      // W_dt bf16
__device__ __nv_bfloat16 g_dth [(size_t)MROWS*DI];   // dt bf16
__device__ __nv_bfloat16 g_yh  [(size_t)MROWS*DI];   // y bf16
__device__ __nv_bfloat16 g_woh [(size_t)DI*DM];      // W_out bf16

// ---------------------------------------------------------------------------
// PTX helpers
// ---------------------------------------------------------------------------
__device__ __forceinline__ unsigned cvta_s(const void* p) {
    return (unsigned)__cvta_generic_to_shared(p);
}
__device__ __forceinline__ void ldsm4(unsigned* r, unsigned a) {
    asm volatile("ldmatrix.sync.aligned.m8n8.x4.shared.b16 {%0,%1,%2,%3}, [%4];"
        : "=r"(r[0]), "=r"(r[1]), "=r"(r[2]), "=r"(r[3]) : "r"(a));
}
__device__ __forceinline__ void ldsm4t(unsigned* r, unsigned a) {
    asm volatile("ldmatrix.sync.aligned.m8n8.x4.trans.shared.b16 {%0,%1,%2,%3}, [%4];"
        : "=r"(r[0]), "=r"(r[1]), "=r"(r[2]), "=r"(r[3]) : "r"(a));
}
__device__ __forceinline__ void mma16816(float* d, const unsigned* a, const unsigned* b) {
    asm volatile("mma.sync.aligned.m16n8k16.row.col.f32.bf16.bf16.f32 "
        "{%0,%1,%2,%3}, {%4,%5,%6,%7}, {%8,%9}, {%0,%1,%2,%3};"
        : "+f"(d[0]), "+f"(d[1]), "+f"(d[2]), "+f"(d[3])
        : "r"(a[0]), "r"(a[1]), "r"(a[2]), "r"(a[3]), "r"(b[0]), "r"(b[1]));
}
__device__ __forceinline__ void cpa16(void* s, const void* g) {
    unsigned sa = cvta_s(s);
    asm volatile("cp.async.cg.shared.global [%0], [%1], 16;" :: "r"(sa), "l"(g));
}
__device__ __forceinline__ void cpcommit() {
    asm volatile("cp.async.commit_group;");
}
template<int N>
__device__ __forceinline__ void cpwait() {
    asm volatile("cp.async.wait_group %0;" :: "n"(N));
}

// ---------------------------------------------------------------------------
// bf16 tensor-core GEMM, cp.async 4-stage pipeline, ONE sync per K-tile.
// CTA tile (64*MF) x 128 x 32; 8 warps (4x2), warp tile (16*MF) x 64.
// EPI: 0 plain fp32 C; 2 +bias[col] softplus -> bf16 Chi;
//      3 +E0 residual -> fp32 C; 4 bf16 Chi only.
// ---------------------------------------------------------------------------
template<int MF, int EPI>
__global__ __launch_bounds__(256) void gemm_bf16(
    const __nv_bfloat16* __restrict__ A, int lda,
    const __nv_bfloat16* __restrict__ B, int ldb,
    float* __restrict__ C, int ldc, int K,
    const float* __restrict__ E0,
    __nv_bfloat16* __restrict__ Chi,
    size_t partStride)
{
    const int BM = 64 * MF;
    const int LDA = 40;
    const int LDB = 136;
    const int A_SZ = BM * LDA;
    const int B_SZ = 32 * LDB;
    const int STAGE = A_SZ + B_SZ;

    extern __shared__ __nv_bfloat16 smem[];

    const int tid  = threadIdx.x;
    const int lane = tid & 31;
    const int wid  = tid >> 5;
    const int wm   = (wid >> 1) * (16 * MF);
    const int wn   = (wid & 1) * 64;
    const int bm   = blockIdx.y * BM;
    const int bn   = blockIdx.x * 128;
    const int kbase = blockIdx.z * K;
    C += (size_t)blockIdx.z * partStride;

    __nv_bfloat16* sA[4];
    __nv_bfloat16* sB[4];
    #pragma unroll
    for (int s = 0; s < 4; s++) {
        sA[s] = smem + s * STAGE;
        sB[s] = sA[s] + A_SZ;
    }

    float acc[MF][8][4];
    #pragma unroll
    for (int i = 0; i < MF; i++) {
        #pragma unroll
        for (int j = 0; j < 8; j++) {
            #pragma unroll
            for (int q = 0; q < 4; q++) acc[i][j][q] = 0.f;
        }
    }

    unsigned aB[4], bB[4];
    #pragma unroll
    for (int s = 0; s < 4; s++) {
        aB[s] = cvta_s(sA[s] + (wm + (lane & 15)) * LDA + ((lane >> 4) << 3));
        bB[s] = cvta_s(sB[s] + (lane & 15) * LDB + wn + ((lane >> 4) << 3));
    }

    const int ar = tid >> 2;
    const int ac = (tid & 3) * 8;
    const int br = tid >> 4;
    const int bc = (tid & 15) * 8;

    const int T = K / 32;

    #define ISSUE_TILE(t_)                                                          \
    {                                                                               \
        const int st_ = (t_) & 3;                                                   \
        const int k0_ = kbase + (t_) * 32;                                          \
        _Pragma("unroll")                                                           \
        for (int p = 0; p < MF; p++) {                                              \
            const int row = p * 64 + ar;                                            \
            cpa16(sA[st_] + row * LDA + ac, A + (size_t)(bm + row) * lda + k0_ + ac); \
        }                                                                           \
        _Pragma("unroll")                                                           \
        for (int p = 0; p < 2; p++) {                                               \
            const int row = p * 16 + br;                                            \
            cpa16(sB[st_] + row * LDB + bc, B + (size_t)(k0_ + row) * ldb + bn + bc); \
        }                                                                           \
        cpcommit();                                                                 \
    }

    ISSUE_TILE(0);
    if (T > 1) ISSUE_TILE(1);
    if (T > 2) ISSUE_TILE(2);

    for (int t = 0; t < T; t++) {
        // guarantee tile t is complete (pending groups are t..min(t+2,T-1))
        if (t + 2 < T) {
            cpwait<2>();
        } else if (t + 1 < T) {
            cpwait<1>();
        } else {
            cpwait<0>();
        }
        __syncthreads();            // data visible; stage (t+3)&3 fully consumed
        if (t + 3 < T) ISSUE_TILE(t + 3);

        const int st = t & 3;
        #pragma unroll
        for (int s = 0; s < 2; s++) {
            unsigned af[MF][4];
            #pragma unroll
            for (int mi = 0; mi < MF; mi++)
                ldsm4(af[mi], aB[st] + (unsigned)((mi * 16 * LDA + s * 16) * 2));
            unsigned bf[8][2];
            #pragma unroll
            for (int pr = 0; pr < 4; pr++) {
                unsigned t4[4];
                ldsm4t(t4, bB[st] + (unsigned)((s * 16 * LDB + pr * 16) * 2));
                bf[2 * pr][0] = t4[0]; bf[2 * pr][1] = t4[1];
                bf[2 * pr + 1][0] = t4[2]; bf[2 * pr + 1][1] = t4[3];
            }
            #pragma unroll
            for (int mi = 0; mi < MF; mi++) {
                #pragma unroll
                for (int nj = 0; nj < 8; nj++)
                    mma16816(acc[mi][nj], af[mi], bf[nj]);
            }
        }
    }
    #undef ISSUE_TILE

    // ---- epilogue ----
    #pragma unroll
    for (int mi = 0; mi < MF; mi++) {
        #pragma unroll
        for (int nj = 0; nj < 8; nj++) {
            const int r0 = bm + wm + mi * 16 + (lane >> 2);
            const int c  = bn + wn + nj * 8 + (lane & 3) * 2;
            #pragma unroll
            for (int hh = 0; hh < 2; hh++) {
                const int r = r0 + hh * 8;
                float vx = acc[mi][nj][2 * hh];
                float vy = acc[mi][nj][2 * hh + 1];
                if (EPI == 2) {
                    vx += E0[c];
                    vy += E0[c + 1];
                    vx = (vx > 20.f) ? vx : log1pf(expf(vx));
                    vy = (vy > 20.f) ? vy : log1pf(expf(vy));
                }
                if (EPI == 3) {
                    const float2 rr = *(const float2*)&E0[(size_t)r * ldc + c];
                    vx += rr.x;
                    vy += rr.y;
                }
                if (EPI == 0 || EPI == 3) {
                    float2 v2; v2.x = vx; v2.y = vy;
                    *(float2*)&C[(size_t)r * ldc + c] = v2;
                }
                if (EPI == 2 || EPI == 4) {
                    __nv_bfloat162 hv;
                    hv.x = __float2bfloat16(vx);
                    hv.y = __float2bfloat16(vy);
                    *(__nv_bfloat162*)&Chi[(size_t)r * ldc + c] = hv;
                }
            }
        }
    }
}

// ---------------------------------------------------------------------------
// GEMM2 split-K reduce: xdbl = p0 + p1 (fp32), xdh = bf16. Also clears
// the scan chain flags (runs before scan_fused each replay).
// ---------------------------------------------------------------------------
__global__ void reduce_xdbl()
{
    const int gi = blockIdx.x * blockDim.x + threadIdx.x;
    if (gi < BB * SEG * NCHG) g_sflag[gi] = 0;
    const int i = gi * 4;
    if (i >= MROWS * NXPP) return;
    float4 a = *(const float4*)&g_P[i];
    float4 b = *(const float4*)&g_P[(size_t)MROWS * NXPP + i];
    float4 v;
    v.x = a.x + b.x; v.y = a.y + b.y; v.z = a.z + b.z; v.w = a.w + b.w;
    *(float4*)&g_xdbl[i] = v;
    __nv_bfloat162 h0; h0.x = __float2bfloat16(v.x); h0.y = __float2bfloat16(v.y);
    __nv_bfloat162 h1; h1.x = __float2bfloat16(v.z); h1.y = __float2bfloat16(v.w);
    *(__nv_bfloat162*)&g_xdh[i]     = h0;
    *(__nv_bfloat162*)&g_xdh[i + 2] = h1;
}

// ---------------------------------------------------------------------------
// Fused conversions: x, W_in, W_out, W_dt (dense) + W_xproj (pad to NXPP),
// all in one launch. Dense regions are n % 4 == 0, processed 4/thread.
// ---------------------------------------------------------------------------
__global__ void cvt_all(
    const float* __restrict__ s0, __nv_bfloat16* __restrict__ d0, int n0,
    const float* __restrict__ s1, __nv_bfloat16* __restrict__ d1, int n1,
    const float* __restrict__ s2, __nv_bfloat16* __restrict__ d2, int n2,
    const float* __restrict__ s3, __nv_bfloat16* __restrict__ d3, int n3,
    const float* __restrict__ sW)   // W_xproj [DI, NXP] -> g_wxh [DI, NXPP]
{
    int i = (blockIdx.x * blockDim.x + threadIdx.x) * 4;
    const int nd = n0 + n1 + n2 + n3;
    if (i < nd) {
        const float* s; __nv_bfloat16* d;
        if (i < n0)                { s = s0 + i;               d = d0 + i; }
        else if (i < n0 + n1)      { s = s1 + (i - n0);        d = d1 + (i - n0); }
        else if (i < n0 + n1 + n2) { s = s2 + (i - n0 - n1);   d = d2 + (i - n0 - n1); }
        else                       { s = s3 + (i - n0 - n1 - n2); d = d3 + (i - n0 - n1 - n2); }
        float4 v = *(const float4*)s;
        __nv_bfloat162 hA; hA.x = __float2bfloat16(v.x); hA.y = __float2bfloat16(v.y);
        __nv_bfloat162 hB; hB.x = __float2bfloat16(v.z); hB.y = __float2bfloat16(v.w);
        *(__nv_bfloat162*)(d)     = hA;
        *(__nv_bfloat162*)(d + 2) = hB;
        return;
    }
    // pad region: indices over DI*NXPP (4 per thread)
    int j = i - nd;
    if (j >= DI * NXPP) return;
    #pragma unroll
    for (int q = 0; q < 4; q++) {
        const int idx = j + q;
        const int row = idx / NXPP;
        const int col = idx % NXPP;
        g_wxh[idx] = __float2bfloat16((col < NXP) ? sW[row * NXP + col] : 0.f);
    }
}

// ---------------------------------------------------------------------------
// Causal depthwise conv (k=4) + bias + silu, register-tiled (CTL=8 steps/thr)
// ---------------------------------------------------------------------------
__global__ __launch_bounds__(256) void conv_silu(
    const float* __restrict__ cw, const float* __restrict__ cb)
{
    const size_t total = (size_t)BB * (LL / CTL) * (DI / 2);
    size_t idx = (size_t)blockIdx.x * blockDim.x + threadIdx.x;
    if (idx >= total) return;
    const int d2 = (int)(idx % (DI / 2)) * 2;
    const int lt = (int)((idx / (DI / 2)) % (LL / CTL));
    const int b  = (int)(idx / ((size_t)(LL / CTL) * (DI / 2)));
    const int l0 = lt * CTL;

    float w0[DCONV], w1[DCONV];
    #pragma unroll
    for (int j = 0; j < DCONV; j++) {
        w0[j] = cw[d2 * DCONV + j];
        w1[j] = cw[(d2 + 1) * DCONV + j];
    }
    const float b0 = cb[d2];
    const float b1 = cb[d2 + 1];

    const __nv_bfloat162* base = (const __nv_bfloat162*)
        (g_xzh + ((size_t)b * LL) * (2 * DI) + d2);
    float x0[CTL + 3], x1[CTL + 3];
    #pragma unroll
    for (int j = 0; j < CTL + 3; j++) {
        const int ls = l0 - 3 + j;
        if (ls >= 0) {
            __nv_bfloat162 xv = base[(size_t)ls * DI];
            x0[j] = __bfloat162float(xv.x);
            x1[j] = __bfloat162float(xv.y);
        } else {
            x0[j] = 0.f;
            x1[j] = 0.f;
        }
    }

    __nv_bfloat162* up = (__nv_bfloat162*)(g_uh + ((size_t)b * LL + l0) * DI + d2);
    #pragma unroll
    for (int t = 0; t < CTL; t++) {
        float a0 = b0, a1 = b1;
        #pragma unroll
        for (int j = 0; j < DCONV; j++) {
            a0 = fmaf(w0[j], x0[t + j], a0);
            a1 = fmaf(w1[j], x1[t + j], a1);
        }
        const float s0 = 1.f / (1.f + __expf(-a0));
        const float s1 = 1.f / (1.f + __expf(-a1));
        __nv_bfloat162 o;
        o.x = __float2bfloat16(a0 * s0);
        o.y = __float2bfloat16(a1 * s1);
        up[(size_t)t * (DI / 2)] = o;
    }
}

// ---------------------------------------------------------------------------
// Fused single-pass chained selective scan. SEG=16 (128-step segments).
// grid(NCHG, BB, SEG) — z (seg) varies slowest so predecessors dispatch first.
// 40 KB dyn smem -> 5 blocks/SM; levels stay resident; chain stays fed.
// ---------------------------------------------------------------------------
__global__ __launch_bounds__(128) void scan_fused(
    const float* __restrict__ A_log, const float* __restrict__ Dvec)
{
    extern __shared__ char smraw[];
    __nv_bfloat16 (*sdt)[32] = (__nv_bfloat16(*)[32])(smraw);
    __nv_bfloat16 (*su )[32] = (__nv_bfloat16(*)[32])(smraw + 8192);
    __nv_bfloat16 (*sz )[32] = (__nv_bfloat16(*)[32])(smraw + 16384);
    float         (*sB )[16] = (float(*)[16])        (smraw + 24576);
    float         (*sC )[16] = (float(*)[16])        (smraw + 32768);

    const int chg = blockIdx.x;
    const int b   = blockIdx.y;
    const int seg = blockIdx.z;
    const int chB = chg * 32;
    const int tid = threadIdx.x;
    const size_t rowBase = (size_t)b * LL + (size_t)seg * SLEN;

    for (int i = tid; i < SLEN * 32; i += 128) {
        int t = i >> 5, c = i & 31;
        sdt[t][c] = g_dth[(rowBase + t) * DI + chB + c];
        su [t][c] = g_uh [(rowBase + t) * DI + chB + c];
        sz [t][c] = g_xzh[(rowBase + t) * (2 * DI) + DI + chB + c];
    }
    for (int i = tid; i < SLEN * 16; i += 128) {
        int t = i >> 4, c = i & 15;
        sB[t][c] = g_xdbl[(rowBase + t) * NXPP + DR + c];
        sC[t][c] = g_xdbl[(rowBase + t) * NXPP + DR + DS + c];
    }
    __syncthreads();

    const int chl = tid >> 2;
    const int ch  = chB + chl;
    const int sg  = tid & 3;
    const int n0  = sg * 4;

    float Ae[4], h[4];
    #pragma unroll
    for (int j = 0; j < 4; j++) {
        Ae[j] = -expf(A_log[ch * DS + n0 + j]) * LOG2E;
        h[j] = 0.f;
    }
    float sumdt = 0.f;

    // ---- local scan (h from 0) ----
    for (int t = 0; t < SLEN; t++) {
        const float dtv = __bfloat162float(sdt[t][chl]);
        const float uv  = __bfloat162float(su[t][chl]);
        const float du  = dtv * uv;
        sumdt += dtv;
        float4 B4 = *(const float4*)&sB[t][n0];
        h[0] = fmaf(exp2f(dtv * Ae[0]), h[0], du * B4.x);
        h[1] = fmaf(exp2f(dtv * Ae[1]), h[1], du * B4.y);
        h[2] = fmaf(exp2f(dtv * Ae[2]), h[2], du * B4.z);
        h[3] = fmaf(exp2f(dtv * Ae[3]), h[3], du * B4.w);
    }

    float P4[4];
    #pragma unroll
    for (int j = 0; j < 4; j++) P4[j] = exp2f(sumdt * Ae[j]);

    // ---- chain: acquire h_in from predecessor, publish inclusive h_out ----
    const size_t hcur = (((size_t)b * SEG + seg) * DI + ch) * DS + n0;
    const int fcur = (b * SEG + seg) * NCHG + chg;
    float hin[4] = {0.f, 0.f, 0.f, 0.f};

    if (seg > 0) {
        const int fprev = fcur - NCHG;
        if (tid == 0) {
            volatile int* fp = &g_sflag[fprev];
            while (*fp == 0) { __nanosleep(64); }
        }
        __syncthreads();
        __threadfence();
        const size_t hprev = hcur - (size_t)DI * DS;
        float4 h4 = *(const float4*)&g_hseg[hprev];
        hin[0] = h4.x; hin[1] = h4.y; hin[2] = h4.z; hin[3] = h4.w;
    }

    {
        float4 ho;
        ho.x = fmaf(P4[0], hin[0], h[0]);
        ho.y = fmaf(P4[1], hin[1], h[1]);
        ho.z = fmaf(P4[2], hin[2], h[2]);
        ho.w = fmaf(P4[3], hin[3], h[3]);
        *(float4*)&g_hseg[hcur] = ho;
    }
    __threadfence();
    __syncthreads();
    if (tid == 0) g_sflag[fcur] = 1;

    // ---- rescan from hin, emit y ----
    const float Dv = Dvec[ch];
    h[0] = hin[0]; h[1] = hin[1]; h[2] = hin[2]; h[3] = hin[3];
    __nv_bfloat16* yph = g_yh + rowBase * DI + ch;

    for (int t = 0; t < SLEN; t++) {
        const float dtv = __bfloat162float(sdt[t][chl]);
        const float uv  = __bfloat162float(su[t][chl]);
        const float du  = dtv * uv;
        float4 B4 = *(const float4*)&sB[t][n0];
        float4 C4 = *(const float4*)&sC[t][n0];
        h[0] = fmaf(exp2f(dtv * Ae[0]), h[0], du * B4.x);
        h[1] = fmaf(exp2f(dtv * Ae[1]), h[1], du * B4.y);
        h[2] = fmaf(exp2f(dtv * Ae[2]), h[2], du * B4.z);
        h[3] = fmaf(exp2f(dtv * Ae[3]), h[3], du * B4.w);

        float yv = h[0] * C4.x;
        yv = fmaf(h[1], C4.y, yv);
        yv = fmaf(h[2], C4.z, yv);
        yv = fmaf(h[3], C4.w, yv);
        yv += __shfl_xor_sync(0xffffffffu, yv, 1);
        yv += __shfl_xor_sync(0xffffffffu, yv, 2);

        if (sg == 0) {
            const float zv  = __bfloat162float(sz[t][chl]);
            const float ys  = fmaf(uv, Dv, yv);
            const float sig = 1.f / (1.f + __expf(-zv));
            const float yo  = ys * (zv * sig);
            yph[(size_t)t * DI] = __float2bfloat16(yo);
        }
    }
}

// ---------------------------------------------------------------------------
// In-place row LayerNorm on d_out (4096 rows x 1024)
// ---------------------------------------------------------------------------
__global__ __launch_bounds__(256) void ln_kernel(
    float* __restrict__ out, const float* __restrict__ gamma,
    const float* __restrict__ beta)
{
    __shared__ float red[8];
    const int row = blockIdx.x;
    float* p = out + (size_t)row * DM;
    const int tid  = threadIdx.x;
    const int lane = tid & 31;
    const int warp = tid >> 5;

    float v[4];
    float s = 0.f;
    #pragma unroll
    for (int i = 0; i < 4; i++) { v[i] = p[tid + 256 * i]; s += v[i]; }
    #pragma unroll
    for (int o = 16; o > 0; o >>= 1) s += __shfl_xor_sync(0xffffffffu, s, o);
    if (lane == 0) red[warp] = s;
    __syncthreads();
    s = 0.f;
    #pragma unroll
    for (int w = 0; w < 8; w++) s += red[w];
    const float mu = s * (1.f / DM);
    __syncthreads();

    float s2 = 0.f;
    #pragma unroll
    for (int i = 0; i < 4; i++) { float d = v[i] - mu; s2 += d * d; }
    #pragma unroll
    for (int o = 16; o > 0; o >>= 1) s2 += __shfl_xor_sync(0xffffffffu, s2, o);
    if (lane == 0) red[warp] = s2;
    __syncthreads();
    s2 = 0.f;
    #pragma unroll
    for (int w = 0; w < 8; w++) s2 += red[w];
    const float rstd = rsqrtf(s2 * (1.f / DM) + 1e-5f);

    #pragma unroll
    for (int i = 0; i < 4; i++) {
        const int col = tid + 256 * i;
        p[col] = (v[i] - mu) * rstd * gamma[col] + beta[col];
    }
}

// ---------------------------------------------------------------------------
// Launcher
// ---------------------------------------------------------------------------
extern "C" void kernel_launch(void* const* d_in, const int* in_sizes, int n_in,
                              void* d_out, int out_size)
{
    const float* x      = (const float*)d_in[0];
    const float* W_in   = (const float*)d_in[1];
    const float* conv_w = (const float*)d_in[2];
    const float* conv_b = (const float*)d_in[3];
    const float* W_xprj = (const float*)d_in[4];
    const float* W_dt   = (const float*)d_in[5];
    const float* b_dt   = (const float*)d_in[6];
    const float* A_log  = (const float*)d_in[7];
    const float* Dvec   = (const float*)d_in[8];
    const float* W_out  = (const float*)d_in[9];
    const float* gamma  = (const float*)d_in[10];
    const float* beta   = (const float*)d_in[11];
    float* out = (float*)d_out;

    float *P;
    cudaGetSymbolAddress((void**)&P, g_P);
    __nv_bfloat16 *xh, *w1h, *xzh, *uh, *wxh, *xdh, *wdh, *dth, *yh, *woh;
    cudaGetSymbolAddress((void**)&xh,  g_xh);
    cudaGetSymbolAddress((void**)&w1h, g_w1h);
    cudaGetSymbolAddress((void**)&xzh, g_xzh);
    cudaGetSymbolAddress((void**)&uh,  g_uh);
    cudaGetSymbolAddress((void**)&wxh, g_wxh);
    cudaGetSymbolAddress((void**)&xdh, g_xdh);
    cudaGetSymbolAddress((void**)&wdh, g_wdh);
    cudaGetSymbolAddress((void**)&dth, g_dth);
    cudaGetSymbolAddress((void**)&yh,  g_yh);
    cudaGetSymbolAddress((void**)&woh, g_woh);

    // dynamic smem sizes (bytes)
    const int SM_MF2 = 4 * (128 * 40 + 32 * 136) * 2;            // 75776
    const int SM_MF1 = 4 * (64 * 40 + 32 * 136) * 2;             // 55296
    const int SM_SC  = 40960;
    cudaFuncSetAttribute(gemm_bf16<2,4>, cudaFuncAttributeMaxDynamicSharedMemorySize, SM_MF2);
    cudaFuncSetAttribute(gemm_bf16<1,0>, cudaFuncAttributeMaxDynamicSharedMemorySize, SM_MF1);
    cudaFuncSetAttribute(gemm_bf16<2,2>, cudaFuncAttributeMaxDynamicSharedMemorySize, SM_MF2);
    cudaFuncSetAttribute(gemm_bf16<2,3>, cudaFuncAttributeMaxDynamicSharedMemorySize, SM_MF2);
    cudaFuncSetAttribute(scan_fused,     cudaFuncAttributeMaxDynamicSharedMemorySize, SM_SC);

    // 0) all conversions in ONE launch (x, W_in, W_out, W_dt, W_xproj pad)
    {
        const int n0 = MROWS * DM;         // x
        const int n1 = DM * 2 * DI;        // W_in
        const int n2 = DI * DM;            // W_out
        const int n3 = DR * DI;            // W_dt
        const int npad = DI * NXPP;        // W_xproj padded
        const int total4 = (n0 + n1 + n2 + n3 + npad) / 4;
        cvt_all<<<(total4 + 255) / 256, 256>>>(x, xh, n0, W_in, w1h, n1,
                                               W_out, woh, n2, W_dt, wdh, n3,
                                               W_xprj);
    }

    // 1) GEMM1: xz = x @ W_in -> bf16  (M=4096, N=4096, K=1024)
    {
        dim3 grid(2 * DI / 128, MROWS / 128);
        gemm_bf16<2, 4><<<grid, 256, SM_MF2>>>(xh, DM, w1h, 2 * DI,
                                               nullptr, 2 * DI, DM, nullptr, xzh, 0);
    }

    // 2) conv + silu -> u (bf16), register-tiled
    {
        size_t n = (size_t)BB * (LL / CTL) * (DI / 2);
        conv_silu<<<(unsigned)((n + 255) / 256), 256>>>(conv_w, conv_b);
    }

    // 3) GEMM2: x_dbl partials, split-K=2 -> g_P; reduce (+flag clear)
    {
        dim3 grid(NXPP / 128, MROWS / 64, 2);
        gemm_bf16<1, 0><<<grid, 256, SM_MF1>>>(uh, DI, wxh, NXPP,
                                               P, NXPP, DI / 2, nullptr, nullptr,
                                               (size_t)MROWS * NXPP);
        reduce_xdbl<<<(MROWS * NXPP / 4 + 255) / 256, 256>>>();
    }

    // 4) GEMM4: dt = softplus(dt_low @ W_dt + b_dt) -> bf16  (M=4096, N=2048, K=64)
    {
        dim3 grid(DI / 128, MROWS / 128);
        gemm_bf16<2, 2><<<grid, 256, SM_MF2>>>(xdh, NXPP, wdh, DI,
                                               nullptr, DI, DR, b_dt, dth, 0);
    }

    // 5) fused single-pass chained scan -> y (bf16), SEG=16
    {
        dim3 grid(NCHG, BB, SEG);
        scan_fused<<<grid, 128, SM_SC>>>(A_log, Dvec);
    }

    // 6) GEMM3: out = y @ W_out + x  (M=4096, N=1024, K=2048; fp32 residual)
    {
        dim3 grid(DM / 128, MROWS / 128);
        gemm_bf16<2, 3><<<grid, 256, SM_MF2>>>(yh, DI, woh, DM,
                                               out, DM, DI, x, nullptr, 0);
    }

    // 7) LayerNorm in-place
    ln_kernel<<<MROWS, 256>>>(out, gamma, beta);
}